// round 12
// baseline (speedup 1.0000x reference)
#include <cuda_runtime.h>
#include <cuda_bf16.h>
#include <mma.h>
#include <cstdint>
#include <cstring>

using namespace nvcuda;

#define BATCH 32768
#define DIN   768
#define HID   3840
#define TOPK  64
#define NSEL  80
#define CAP   512
#define T0FILT 1.55f

// ---------------- scratch ----------------
__device__ float g_h[(size_t)BATCH * HID];
__device__ float g_wdecT[(size_t)HID * DIN];
__device__ int   g_tidx[(size_t)BATCH * TOPK];
__device__ float g_tval[(size_t)BATCH * TOPK];
__device__ __align__(16) __nv_bfloat16 g_xb[(size_t)BATCH * DIN];
__device__ __align__(16) __nv_bfloat16 g_wb[(size_t)HID * DIN];

// ======================= bf16 conversion kernels =======================
__global__ void __launch_bounds__(192) conv_x_kernel(const float* __restrict__ x,
                                                     const float* __restrict__ b_pre) {
    const int row = blockIdx.x;
    const int c4 = threadIdx.x;  // 192*4 = 768
    const float4 xv = ((const float4*)(x + (size_t)row * DIN))[c4];
    const float4 bp = ((const float4*)b_pre)[c4];
    __nv_bfloat16 h0 = __float2bfloat16(xv.x - bp.x);
    __nv_bfloat16 h1 = __float2bfloat16(xv.y - bp.y);
    __nv_bfloat16 h2 = __float2bfloat16(xv.z - bp.z);
    __nv_bfloat16 h3 = __float2bfloat16(xv.w - bp.w);
    uint2 p;
    p.x = (uint32_t)*(unsigned short*)&h0 | ((uint32_t)*(unsigned short*)&h1 << 16);
    p.y = (uint32_t)*(unsigned short*)&h2 | ((uint32_t)*(unsigned short*)&h3 << 16);
    ((uint2*)(g_xb + (size_t)row * DIN))[c4] = p;
}

__global__ void __launch_bounds__(192) conv_w_kernel(const float* __restrict__ W) {
    const int row = blockIdx.x;
    const int c4 = threadIdx.x;
    const float4 wv = ((const float4*)(W + (size_t)row * DIN))[c4];
    __nv_bfloat16 h0 = __float2bfloat16(wv.x);
    __nv_bfloat16 h1 = __float2bfloat16(wv.y);
    __nv_bfloat16 h2 = __float2bfloat16(wv.z);
    __nv_bfloat16 h3 = __float2bfloat16(wv.w);
    uint2 p;
    p.x = (uint32_t)*(unsigned short*)&h0 | ((uint32_t)*(unsigned short*)&h1 << 16);
    p.y = (uint32_t)*(unsigned short*)&h2 | ((uint32_t)*(unsigned short*)&h3 << 16);
    ((uint2*)(g_wb + (size_t)row * DIN))[c4] = p;
}

// ======================= WMMA bf16 screening GEMM (verified in round 11) =======================
#define GBM 128
#define GBN 128
#define GBK 32
#define LDSB 40
#define BUF_ELEMS (GBM * LDSB)
#define GSMEM_BYTES (4 * BUF_ELEMS * 2)

__global__ void __launch_bounds__(256, 2) enc_gemm_wmma(const float* __restrict__ b_enc) {
    extern __shared__ char gsm[];
    __nv_bfloat16* Abuf = (__nv_bfloat16*)gsm;
    __nv_bfloat16* Bbuf = (__nv_bfloat16*)(gsm + 2 * BUF_ELEMS * 2);
    float* stage = (float*)gsm;

    const int bm = blockIdx.y * GBM;
    const int bn = blockIdx.x * GBN;
    const int tid = threadIdx.x, lane = tid & 31, wid = tid >> 5;
    const int wm = wid & 3;
    const int wn = wid >> 2;

    wmma::fragment<wmma::accumulator, 16, 16, 16, float> c[2][4];
    #pragma unroll
    for (int i = 0; i < 2; ++i)
        #pragma unroll
        for (int j = 0; j < 4; ++j) wmma::fill_fragment(c[i][j], 0.f);

    uint4 ra[2], rb[2];
    #pragma unroll
    for (int i = 0; i < 2; ++i) {
        const int idx = tid + 256 * i;
        const int r = idx >> 2, seg = idx & 3;
        ra[i] = *(const uint4*)(g_xb + (size_t)(bm + r) * DIN + seg * 8);
        rb[i] = *(const uint4*)(g_wb + (size_t)(bn + r) * DIN + seg * 8);
    }
    #pragma unroll
    for (int i = 0; i < 2; ++i) {
        const int idx = tid + 256 * i;
        const int r = idx >> 2, seg = idx & 3;
        *(uint4*)(Abuf + r * LDSB + seg * 8) = ra[i];
        *(uint4*)(Bbuf + r * LDSB + seg * 8) = rb[i];
    }
    __syncthreads();

    int buf = 0;
    const int NS = DIN / GBK;  // 24

    #pragma unroll 1
    for (int s = 0; s < NS; ++s) {
        const bool has_next = (s + 1 < NS);
        if (has_next) {
            const int k0 = (s + 1) * GBK;
            #pragma unroll
            for (int i = 0; i < 2; ++i) {
                const int idx = tid + 256 * i;
                const int r = idx >> 2, seg = idx & 3;
                ra[i] = *(const uint4*)(g_xb + (size_t)(bm + r) * DIN + k0 + seg * 8);
                rb[i] = *(const uint4*)(g_wb + (size_t)(bn + r) * DIN + k0 + seg * 8);
            }
        }

        const __nv_bfloat16* Ab = Abuf + buf * BUF_ELEMS;
        const __nv_bfloat16* Bb = Bbuf + buf * BUF_ELEMS;
        #pragma unroll
        for (int ks = 0; ks < 2; ++ks) {
            wmma::fragment<wmma::matrix_a, 16, 16, 16, __nv_bfloat16, wmma::row_major> af[2];
            wmma::fragment<wmma::matrix_b, 16, 16, 16, __nv_bfloat16, wmma::col_major> bfr[4];
            #pragma unroll
            for (int i = 0; i < 2; ++i)
                wmma::load_matrix_sync(af[i], Ab + (wm * 32 + 16 * i) * LDSB + ks * 16, LDSB);
            #pragma unroll
            for (int j = 0; j < 4; ++j)
                wmma::load_matrix_sync(bfr[j], Bb + (wn * 64 + 16 * j) * LDSB + ks * 16, LDSB);
            #pragma unroll
            for (int i = 0; i < 2; ++i)
                #pragma unroll
                for (int j = 0; j < 4; ++j)
                    wmma::mma_sync(c[i][j], af[i], bfr[j], c[i][j]);
        }

        if (has_next) {
            const int nb = buf ^ 1;
            #pragma unroll
            for (int i = 0; i < 2; ++i) {
                const int idx = tid + 256 * i;
                const int r = idx >> 2, seg = idx & 3;
                *(uint4*)(Abuf + nb * BUF_ELEMS + r * LDSB + seg * 8) = ra[i];
                *(uint4*)(Bbuf + nb * BUF_ELEMS + r * LDSB + seg * 8) = rb[i];
            }
        }
        __syncthreads();
        buf ^= 1;
    }

    float* wstage = stage + wid * 320;
    const int rr = lane >> 1;
    const int cc = (lane & 1) * 8;
    #pragma unroll
    for (int i = 0; i < 2; ++i) {
        #pragma unroll
        for (int j = 0; j < 4; ++j) {
            wmma::store_matrix_sync(wstage, c[i][j], 20, wmma::mem_row_major);
            __syncwarp();
            const int m = bm + wm * 32 + 16 * i + rr;
            const int n = bn + wn * 64 + 16 * j + cc;
            float4 v0 = *(float4*)(wstage + rr * 20 + cc);
            float4 v1 = *(float4*)(wstage + rr * 20 + cc + 4);
            const float4 be0 = *(const float4*)(b_enc + n);
            const float4 be1 = *(const float4*)(b_enc + n + 4);
            v0.x += be0.x; v0.y += be0.y; v0.z += be0.z; v0.w += be0.w;
            v1.x += be1.x; v1.y += be1.y; v1.z += be1.z; v1.w += be1.w;
            *(float4*)(g_h + (size_t)m * HID + n)     = v0;
            *(float4*)(g_h + (size_t)m * HID + n + 4) = v1;
            __syncwarp();
        }
    }
}

// ======================= W_dec [D,H] -> W_decT [H,D] =======================
__global__ void transpose_kernel(const float* __restrict__ in)
{
    __shared__ float t[32][33];
    const int bx = blockIdx.x * 32;
    const int by = blockIdx.y * 32;
    const int x = bx + threadIdx.x;
    #pragma unroll
    for (int j = 0; j < 32; j += 8)
        t[threadIdx.y + j][threadIdx.x] = in[(size_t)(by + threadIdx.y + j) * HID + x];
    __syncthreads();
    const int x2 = by + threadIdx.x;
    #pragma unroll
    for (int j = 0; j < 32; j += 8)
        g_wdecT[(size_t)(bx + threadIdx.y + j) * DIN + x2] = t[threadIdx.x][threadIdx.y + j];
}

// ======================= approx top-80 + fp32-chain rescore (jax-matching) =======================
// The rescore reproduces the round-1 fp32 GEMM arithmetic bit-exactly:
// acc = 0; for k ascending: acc = fmaf(x_c[k], W[j][k], acc); val = acc + b_enc[j].
// This matches the reference's fp32 rounding behavior at ultra-tight boundaries
// (an error-free "true" rescore provably flips ~3 of them -> 1.54e-3).
__global__ void __launch_bounds__(128) topk_kernel(
    float* __restrict__ h_sparse,
    const float* __restrict__ x, const float* __restrict__ W_enc,
    const float* __restrict__ b_pre, const float* __restrict__ b_enc)
{
    const int row = blockIdx.x;
    __shared__ float sv[HID];
    __shared__ float xc[DIN];
    __shared__ float cv[CAP];
    __shared__ int   ci[CAP];
    __shared__ int   s_cnt;
    __shared__ int   sel_i[NSEL];
    __shared__ float s_exv[NSEL];
    __shared__ int   out_i[TOPK];
    __shared__ float out_v[TOPK];

    const int tid = threadIdx.x;
    const float* hr = g_h + (size_t)row * HID;
    if (tid == 0) s_cnt = 0;

    // exact centered x row into smem (b_pre subtraction same as round-1 As path)
    {
        const float4* x4 = (const float4*)(x + (size_t)row * DIN);
        const float4* b4 = (const float4*)b_pre;
        for (int i = tid; i < DIN / 4; i += 128) {
            float4 xv = x4[i], bp = b4[i];
            xv.x -= bp.x; xv.y -= bp.y; xv.z -= bp.z; xv.w -= bp.w;
            ((float4*)xc)[i] = xv;
        }
    }
    __syncthreads();

    // prefilter candidates from approx h
    for (int i = tid; i < HID / 4; i += 128) {
        float4 v = ((const float4*)hr)[i];
        ((float4*)sv)[i] = v;
        const int base = i * 4;
        if (v.x > T0FILT) { int p = atomicAdd(&s_cnt, 1); if (p < CAP) { cv[p] = v.x; ci[p] = base + 0; } }
        if (v.y > T0FILT) { int p = atomicAdd(&s_cnt, 1); if (p < CAP) { cv[p] = v.y; ci[p] = base + 1; } }
        if (v.z > T0FILT) { int p = atomicAdd(&s_cnt, 1); if (p < CAP) { cv[p] = v.z; ci[p] = base + 2; } }
        if (v.w > T0FILT) { int p = atomicAdd(&s_cnt, 1); if (p < CAP) { cv[p] = v.w; ci[p] = base + 3; } }
    }
    __syncthreads();
    const int cnt = s_cnt;
    const bool fallback = (cnt < NSEL) || (cnt > CAP);

    // approx top-80 selection (warp 0)
    if (tid < 32) {
        if (!fallback) {
            for (int it = 0; it < NSEL; ++it) {
                float best = -3.0e38f; int bi = 0x7FFFFFFF; int bc = 0;
                for (int c = tid; c < cnt; c += 32) {
                    float v = cv[c]; int id = ci[c];
                    if (v > best || (v == best && id < bi)) { best = v; bi = id; bc = c; }
                }
                #pragma unroll
                for (int o = 16; o > 0; o >>= 1) {
                    float ov = __shfl_xor_sync(0xffffffffu, best, o);
                    int   oi = __shfl_xor_sync(0xffffffffu, bi, o);
                    int   oc = __shfl_xor_sync(0xffffffffu, bc, o);
                    if (ov > best || (ov == best && oi < bi)) { best = ov; bi = oi; bc = oc; }
                }
                if (tid == 0) { cv[bc] = -3.0e38f; sel_i[it] = bi; }
                __syncwarp();
            }
        } else {
            for (int it = 0; it < NSEL; ++it) {
                float best = -3.0e38f; int bi = 0x7FFFFFFF;
                for (int c = tid; c < HID; c += 32) {
                    float v = sv[c];
                    if (v > best || (v == best && c < bi)) { best = v; bi = c; }
                }
                #pragma unroll
                for (int o = 16; o > 0; o >>= 1) {
                    float ov = __shfl_xor_sync(0xffffffffu, best, o);
                    int   oi = __shfl_xor_sync(0xffffffffu, bi, o);
                    if (ov > best || (ov == best && oi < bi)) { best = ov; bi = oi; }
                }
                if (tid == 0) { sv[bi] = -3.0e38f; sel_i[it] = bi; }
                __syncwarp();
            }
        }
    }
    __syncthreads();

    // fp32 serial k-ascending rescore (bit-identical to round-1 GEMM arithmetic)
    if (tid < NSEL) {
        const int j = sel_i[tid];
        const float* wr = W_enc + (size_t)j * DIN;
        float acc = 0.f;
        #pragma unroll 8
        for (int k = 0; k < DIN; ++k)
            acc = fmaf(xc[k], wr[k], acc);
        s_exv[tid] = acc + b_enc[j];
    }
    __syncthreads();

    // re-rank by (fp32 value desc, index asc); keep ranks 0..63
    if (tid < NSEL) {
        const float mv = s_exv[tid];
        const int mi = sel_i[tid];
        int rank = 0;
        for (int m = 0; m < NSEL; ++m) {
            const float ov = s_exv[m];
            const int oi = sel_i[m];
            if (ov > mv || (ov == mv && oi < mi)) ++rank;
        }
        if (rank < TOPK) {
            out_i[rank] = mi;
            out_v[rank] = mv > 0.f ? mv : 0.f;
        }
    }
    __syncthreads();

    // scatter
    float* orow = h_sparse + (size_t)row * HID;
    const float4 z4 = make_float4(0.f, 0.f, 0.f, 0.f);
    for (int i = tid; i < HID / 4; i += 128) ((float4*)orow)[i] = z4;
    __syncthreads();
    if (tid < TOPK) {
        orow[out_i[tid]] = out_v[tid];
        g_tidx[(size_t)row * TOPK + tid] = out_i[tid];
        g_tval[(size_t)row * TOPK + tid] = out_v[tid];
    }
}

// ======================= sparse decoder =======================
__global__ void __launch_bounds__(192) dec_kernel(
    const float* __restrict__ b_pre, float* __restrict__ xrec)
{
    const int row = blockIdx.x;
    __shared__ int   si[TOPK];
    __shared__ float svl[TOPK];
    const int tid = threadIdx.x;
    if (tid < TOPK) {
        si[tid]  = g_tidx[(size_t)row * TOPK + tid];
        svl[tid] = g_tval[(size_t)row * TOPK + tid];
    }
    __syncthreads();

    float4 acc = ((const float4*)b_pre)[tid];
    #pragma unroll 4
    for (int k = 0; k < TOPK; ++k) {
        const float v = svl[k];
        const float4 wv = ((const float4*)(g_wdecT + (size_t)si[k] * DIN))[tid];
        acc.x = fmaf(v, wv.x, acc.x);
        acc.y = fmaf(v, wv.y, acc.y);
        acc.z = fmaf(v, wv.z, acc.z);
        acc.w = fmaf(v, wv.w, acc.w);
    }
    ((float4*)(xrec + (size_t)row * DIN))[tid] = acc;
}

// ======================= launch =======================
extern "C" void kernel_launch(void* const* d_in, const int* in_sizes, int n_in,
                              void* d_out, int out_size)
{
    const float* x     = (const float*)d_in[0];
    const float* W_enc = (const float*)d_in[1];
    const float* b_enc = (const float*)d_in[2];
    const float* W_dec = (const float*)d_in[3];
    const float* b_pre = (const float*)d_in[4];

    float* out      = (float*)d_out;
    float* xrec     = out;                        // [B, 768]
    float* h_sparse = out + (size_t)BATCH * DIN;  // [B, 3840]

    cudaFuncSetAttribute(enc_gemm_wmma, cudaFuncAttributeMaxDynamicSharedMemorySize, GSMEM_BYTES);

    conv_x_kernel<<<BATCH, 192>>>(x, b_pre);
    conv_w_kernel<<<HID, 192>>>(W_enc);
    transpose_kernel<<<dim3(HID / 32, DIN / 32), dim3(32, 8)>>>(W_dec);

    enc_gemm_wmma<<<dim3(HID / GBN, BATCH / GBM), 256, GSMEM_BYTES>>>(b_enc);

    topk_kernel<<<BATCH, 128>>>(h_sparse, x, W_enc, b_pre, b_enc);
    dec_kernel<<<BATCH, 192>>>(b_pre, xrec);
}

// round 13
// speedup vs baseline: 2.0127x; 2.0127x over previous
#include <cuda_runtime.h>
#include <cuda_bf16.h>
#include <mma.h>
#include <cstdint>
#include <cstring>

using namespace nvcuda;

#define BATCH 32768
#define DIN   768
#define HID   3840
#define TOPK  64
#define NSEL  80
#define CAP   512
#define T0FILT 1.55f
#define GAPEPS 1e-4f
#define BANDCAP 32

// ---------------- scratch ----------------
__device__ float g_h[(size_t)BATCH * HID];
__device__ float g_wdecT[(size_t)HID * DIN];
__device__ int   g_tidx[(size_t)BATCH * TOPK];
__device__ float g_tval[(size_t)BATCH * TOPK];
__device__ __align__(16) __nv_bfloat16 g_xb[(size_t)BATCH * DIN];
__device__ __align__(16) __nv_bfloat16 g_wb[(size_t)HID * DIN];

// ---------------- error-free float-float primitives ----------------
__device__ __forceinline__ void twosum(float a, float b, float& s, float& e) {
    s = a + b;
    float bb = s - a;
    e = (a - (s - bb)) + (b - bb);
}
__device__ __forceinline__ void dfadd(float& hi, float& lo, float bhi, float blo) {
    float s, e;
    twosum(hi, bhi, s, e);
    e += lo + blo;
    float s2, e2;
    twosum(s, e, s2, e2);
    hi = s2; lo = e2;
}

// ======================= bf16 conversion kernels =======================
__global__ void __launch_bounds__(192) conv_x_kernel(const float* __restrict__ x,
                                                     const float* __restrict__ b_pre) {
    const int row = blockIdx.x;
    const int c4 = threadIdx.x;
    const float4 xv = ((const float4*)(x + (size_t)row * DIN))[c4];
    const float4 bp = ((const float4*)b_pre)[c4];
    __nv_bfloat16 h0 = __float2bfloat16(xv.x - bp.x);
    __nv_bfloat16 h1 = __float2bfloat16(xv.y - bp.y);
    __nv_bfloat16 h2 = __float2bfloat16(xv.z - bp.z);
    __nv_bfloat16 h3 = __float2bfloat16(xv.w - bp.w);
    uint2 p;
    p.x = (uint32_t)*(unsigned short*)&h0 | ((uint32_t)*(unsigned short*)&h1 << 16);
    p.y = (uint32_t)*(unsigned short*)&h2 | ((uint32_t)*(unsigned short*)&h3 << 16);
    ((uint2*)(g_xb + (size_t)row * DIN))[c4] = p;
}

__global__ void __launch_bounds__(192) conv_w_kernel(const float* __restrict__ W) {
    const int row = blockIdx.x;
    const int c4 = threadIdx.x;
    const float4 wv = ((const float4*)(W + (size_t)row * DIN))[c4];
    __nv_bfloat16 h0 = __float2bfloat16(wv.x);
    __nv_bfloat16 h1 = __float2bfloat16(wv.y);
    __nv_bfloat16 h2 = __float2bfloat16(wv.z);
    __nv_bfloat16 h3 = __float2bfloat16(wv.w);
    uint2 p;
    p.x = (uint32_t)*(unsigned short*)&h0 | ((uint32_t)*(unsigned short*)&h1 << 16);
    p.y = (uint32_t)*(unsigned short*)&h2 | ((uint32_t)*(unsigned short*)&h3 << 16);
    ((uint2*)(g_wb + (size_t)row * DIN))[c4] = p;
}

// ======================= WMMA bf16 screening GEMM (verified R11/R12) =======================
#define GBM 128
#define GBN 128
#define GBK 32
#define LDSB 40
#define BUF_ELEMS (GBM * LDSB)
#define GSMEM_BYTES (4 * BUF_ELEMS * 2)

__global__ void __launch_bounds__(256, 2) enc_gemm_wmma(const float* __restrict__ b_enc) {
    extern __shared__ char gsm[];
    __nv_bfloat16* Abuf = (__nv_bfloat16*)gsm;
    __nv_bfloat16* Bbuf = (__nv_bfloat16*)(gsm + 2 * BUF_ELEMS * 2);
    float* stage = (float*)gsm;

    const int bm = blockIdx.y * GBM;
    const int bn = blockIdx.x * GBN;
    const int tid = threadIdx.x, lane = tid & 31, wid = tid >> 5;
    const int wm = wid & 3;
    const int wn = wid >> 2;

    wmma::fragment<wmma::accumulator, 16, 16, 16, float> c[2][4];
    #pragma unroll
    for (int i = 0; i < 2; ++i)
        #pragma unroll
        for (int j = 0; j < 4; ++j) wmma::fill_fragment(c[i][j], 0.f);

    uint4 ra[2], rb[2];
    #pragma unroll
    for (int i = 0; i < 2; ++i) {
        const int idx = tid + 256 * i;
        const int r = idx >> 2, seg = idx & 3;
        ra[i] = *(const uint4*)(g_xb + (size_t)(bm + r) * DIN + seg * 8);
        rb[i] = *(const uint4*)(g_wb + (size_t)(bn + r) * DIN + seg * 8);
    }
    #pragma unroll
    for (int i = 0; i < 2; ++i) {
        const int idx = tid + 256 * i;
        const int r = idx >> 2, seg = idx & 3;
        *(uint4*)(Abuf + r * LDSB + seg * 8) = ra[i];
        *(uint4*)(Bbuf + r * LDSB + seg * 8) = rb[i];
    }
    __syncthreads();

    int buf = 0;
    const int NS = DIN / GBK;

    #pragma unroll 1
    for (int s = 0; s < NS; ++s) {
        const bool has_next = (s + 1 < NS);
        if (has_next) {
            const int k0 = (s + 1) * GBK;
            #pragma unroll
            for (int i = 0; i < 2; ++i) {
                const int idx = tid + 256 * i;
                const int r = idx >> 2, seg = idx & 3;
                ra[i] = *(const uint4*)(g_xb + (size_t)(bm + r) * DIN + k0 + seg * 8);
                rb[i] = *(const uint4*)(g_wb + (size_t)(bn + r) * DIN + k0 + seg * 8);
            }
        }

        const __nv_bfloat16* Ab = Abuf + buf * BUF_ELEMS;
        const __nv_bfloat16* Bb = Bbuf + buf * BUF_ELEMS;
        #pragma unroll
        for (int ks = 0; ks < 2; ++ks) {
            wmma::fragment<wmma::matrix_a, 16, 16, 16, __nv_bfloat16, wmma::row_major> af[2];
            wmma::fragment<wmma::matrix_b, 16, 16, 16, __nv_bfloat16, wmma::col_major> bfr[4];
            #pragma unroll
            for (int i = 0; i < 2; ++i)
                wmma::load_matrix_sync(af[i], Ab + (wm * 32 + 16 * i) * LDSB + ks * 16, LDSB);
            #pragma unroll
            for (int j = 0; j < 4; ++j)
                wmma::load_matrix_sync(bfr[j], Bb + (wn * 64 + 16 * j) * LDSB + ks * 16, LDSB);
            #pragma unroll
            for (int i = 0; i < 2; ++i)
                #pragma unroll
                for (int j = 0; j < 4; ++j)
                    wmma::mma_sync(c[i][j], af[i], bfr[j], c[i][j]);
        }

        if (has_next) {
            const int nb = buf ^ 1;
            #pragma unroll
            for (int i = 0; i < 2; ++i) {
                const int idx = tid + 256 * i;
                const int r = idx >> 2, seg = idx & 3;
                *(uint4*)(Abuf + nb * BUF_ELEMS + r * LDSB + seg * 8) = ra[i];
                *(uint4*)(Bbuf + nb * BUF_ELEMS + r * LDSB + seg * 8) = rb[i];
            }
        }
        __syncthreads();
        buf ^= 1;
    }

    float* wstage = stage + wid * 320;
    const int rr = lane >> 1;
    const int cc = (lane & 1) * 8;
    #pragma unroll
    for (int i = 0; i < 2; ++i) {
        #pragma unroll
        for (int j = 0; j < 4; ++j) {
            wmma::store_matrix_sync(wstage, c[i][j], 20, wmma::mem_row_major);
            __syncwarp();
            const int m = bm + wm * 32 + 16 * i + rr;
            const int n = bn + wn * 64 + 16 * j + cc;
            float4 v0 = *(float4*)(wstage + rr * 20 + cc);
            float4 v1 = *(float4*)(wstage + rr * 20 + cc + 4);
            const float4 be0 = *(const float4*)(b_enc + n);
            const float4 be1 = *(const float4*)(b_enc + n + 4);
            v0.x += be0.x; v0.y += be0.y; v0.z += be0.z; v0.w += be0.w;
            v1.x += be1.x; v1.y += be1.y; v1.z += be1.z; v1.w += be1.w;
            *(float4*)(g_h + (size_t)m * HID + n)     = v0;
            *(float4*)(g_h + (size_t)m * HID + n + 4) = v1;
            __syncwarp();
        }
    }
}

// ======================= W_dec [D,H] -> W_decT [H,D] =======================
__global__ void transpose_kernel(const float* __restrict__ in)
{
    __shared__ float t[32][33];
    const int bx = blockIdx.x * 32;
    const int by = blockIdx.y * 32;
    const int x = bx + threadIdx.x;
    #pragma unroll
    for (int j = 0; j < 32; j += 8)
        t[threadIdx.y + j][threadIdx.x] = in[(size_t)(by + threadIdx.y + j) * HID + x];
    __syncthreads();
    const int x2 = by + threadIdx.x;
    #pragma unroll
    for (int j = 0; j < 32; j += 8)
        g_wdecT[(size_t)(bx + threadIdx.y + j) * DIN + x2] = t[threadIdx.x][threadIdx.y + j];
}

// ======================= topk: screen -> exact rescore -> boundary band (serial fp32) =======================
// Membership = jax top-64 membership. Exact (error-free) values decide membership
// except within a 1e-4 band at the 63/64 boundary, where the serial fp32 k-ascending
// chain (validated to match jax's rounding decisions in R1/8/10/12) decides.
__global__ void __launch_bounds__(128) topk_kernel(
    float* __restrict__ h_sparse,
    const float* __restrict__ x, const float* __restrict__ W_enc,
    const float* __restrict__ b_pre, const float* __restrict__ b_enc)
{
    const int row = blockIdx.x;
    __shared__ float xc[DIN];
    __shared__ float cv[CAP];
    __shared__ int   ci[CAP];
    __shared__ int   s_cnt, s_nsel, s_nband, s_doband;
    __shared__ int   sel_i[NSEL];
    __shared__ float s_hi[NSEL], s_lo[NSEL];
    __shared__ double s_ex[NSEL];
    __shared__ int   s_rank[NSEL];
    __shared__ unsigned char s_member[NSEL];
    __shared__ float s_v63, s_v64;
    __shared__ int   bnd_sl[BANDCAP];
    __shared__ float bnd_sv[BANDCAP];
    __shared__ int   out_i[TOPK];
    __shared__ float out_v[TOPK];

    const int tid = threadIdx.x, lane = tid & 31, wrp = tid >> 5;
    const float* hr = g_h + (size_t)row * HID;

    if (tid == 0) { s_cnt = 0; s_nband = 0; s_doband = 0; s_v63 = 3.0e38f; s_v64 = -3.0e38f; }

    // exact centered x row into smem
    {
        const float4* x4 = (const float4*)(x + (size_t)row * DIN);
        const float4* b4 = (const float4*)b_pre;
        for (int i = tid; i < DIN / 4; i += 128) {
            float4 xv = x4[i], bp = b4[i];
            xv.x -= bp.x; xv.y -= bp.y; xv.z -= bp.z; xv.w -= bp.w;
            ((float4*)xc)[i] = xv;
        }
    }
    __syncthreads();

    // prefilter candidates from approx h
    for (int i = tid; i < HID / 4; i += 128) {
        float4 v = ((const float4*)hr)[i];
        const int base = i * 4;
        if (v.x > T0FILT) { int p = atomicAdd(&s_cnt, 1); if (p < CAP) { cv[p] = v.x; ci[p] = base + 0; } }
        if (v.y > T0FILT) { int p = atomicAdd(&s_cnt, 1); if (p < CAP) { cv[p] = v.y; ci[p] = base + 1; } }
        if (v.z > T0FILT) { int p = atomicAdd(&s_cnt, 1); if (p < CAP) { cv[p] = v.z; ci[p] = base + 2; } }
        if (v.w > T0FILT) { int p = atomicAdd(&s_cnt, 1); if (p < CAP) { cv[p] = v.w; ci[p] = base + 3; } }
    }
    __syncthreads();
    const int cnt = s_cnt;
    const bool fb = (cnt < TOPK) || (cnt > CAP);

    // candidate set selection
    if (!fb && cnt <= NSEL) {
        if (tid == 0) s_nsel = cnt;
        if (tid < cnt) sel_i[tid] = ci[tid];
    } else if (!fb) {
        if (tid == 0) s_nsel = NSEL;
        if (tid < 32) {
            for (int it = 0; it < NSEL; ++it) {
                float best = -3.0e38f; int bi = 0x7FFFFFFF; int bc = 0;
                for (int c = lane; c < cnt; c += 32) {
                    float v = cv[c]; int id = ci[c];
                    if (v > best || (v == best && id < bi)) { best = v; bi = id; bc = c; }
                }
                #pragma unroll
                for (int o = 16; o > 0; o >>= 1) {
                    float ov = __shfl_xor_sync(0xffffffffu, best, o);
                    int   oi = __shfl_xor_sync(0xffffffffu, bi, o);
                    int   oc = __shfl_xor_sync(0xffffffffu, bc, o);
                    if (ov > best || (ov == best && oi < bi)) { best = ov; bi = oi; bc = oc; }
                }
                if (lane == 0) { cv[bc] = -3.0e38f; sel_i[it] = bi; }
                __syncwarp();
            }
        }
    } else {
        // rare fallback: select approx top-80 straight from g_h (scratch; clobbered)
        if (tid == 0) s_nsel = NSEL;
        if (tid < 32) {
            float* hrm = g_h + (size_t)row * HID;
            for (int it = 0; it < NSEL; ++it) {
                float best = -3.0e38f; int bi = 0x7FFFFFFF;
                for (int c = lane; c < HID; c += 32) {
                    float v = hrm[c];
                    if (v > best || (v == best && c < bi)) { best = v; bi = c; }
                }
                #pragma unroll
                for (int o = 16; o > 0; o >>= 1) {
                    float ov = __shfl_xor_sync(0xffffffffu, best, o);
                    int   oi = __shfl_xor_sync(0xffffffffu, bi, o);
                    if (ov > best || (ov == best && oi < bi)) { best = ov; bi = oi; }
                }
                if (lane == 0) { hrm[bi] = -3.0e38f; sel_i[it] = bi; }
                __syncwarp();
            }
        }
    }
    __syncthreads();
    const int nsel = s_nsel;

    // warp-parallel exact rescore (Kahan + error-free TwoSum reduce), coalesced float4
    for (int q = 0; q < NSEL / 4; ++q) {
        const int sl = wrp * (NSEL / 4) + q;
        if (sl < nsel) {
            const int j = sel_i[sl];
            const float4* wr4 = (const float4*)(W_enc + (size_t)j * DIN);
            const float4* xc4 = (const float4*)xc;
            float s = 0.f, comp = 0.f;
            for (int f = lane; f < DIN / 4; f += 32) {
                const float4 xv = xc4[f];
                const float4 wv = wr4[f];
                float term, y, tt;
                term = xv.x * wv.x; y = term - comp; tt = s + y; comp = (tt - s) - y; s = tt;
                term = xv.y * wv.y; y = term - comp; tt = s + y; comp = (tt - s) - y; s = tt;
                term = xv.z * wv.z; y = term - comp; tt = s + y; comp = (tt - s) - y; s = tt;
                term = xv.w * wv.w; y = term - comp; tt = s + y; comp = (tt - s) - y; s = tt;
            }
            float hi, lo;
            twosum(s, -comp, hi, lo);
            #pragma unroll
            for (int o = 16; o > 0; o >>= 1) {
                const float ohi = __shfl_xor_sync(0xffffffffu, hi, o);
                const float olo = __shfl_xor_sync(0xffffffffu, lo, o);
                dfadd(hi, lo, ohi, olo);
            }
            if (lane == 0) {
                dfadd(hi, lo, b_enc[j], 0.f);
                s_hi[sl] = hi; s_lo[sl] = lo;
            }
        }
    }
    __syncthreads();

    if (tid < nsel) s_ex[tid] = (double)s_hi[tid] + (double)s_lo[tid];
    __syncthreads();

    // rank by exact value (desc, idx asc); default membership = rank < 64
    if (tid < nsel) {
        const double mv = s_ex[tid];
        const int mi = sel_i[tid];
        int rank = 0;
        for (int m = 0; m < nsel; ++m) {
            const double ov = s_ex[m];
            const int oi = sel_i[m];
            if (ov > mv || (ov == mv && oi < mi)) ++rank;
        }
        s_rank[tid] = rank;
        s_member[tid] = (rank < TOPK) ? 1 : 0;
        if (rank == TOPK - 1) s_v63 = (float)mv;
        if (rank == TOPK)     s_v64 = (float)mv;
    }
    __syncthreads();

    if (tid == 0 && nsel > TOPK && (s_v63 - s_v64) < GAPEPS) s_doband = 1;
    __syncthreads();

    if (s_doband) {
        // collect boundary band
        if (tid < nsel) {
            const float v = (float)s_ex[tid];
            if (v >= s_v64 - GAPEPS && v <= s_v63 + GAPEPS) {
                int p = atomicAdd(&s_nband, 1);
                if (p < BANDCAP) bnd_sl[p] = tid;
            }
        }
        __syncthreads();
        const int nb = min(s_nband, BANDCAP);
        // serial fp32 k-ascending rescore of band members (jax-matching arithmetic, R12-verified)
        if (tid < nb) {
            const int sl = bnd_sl[tid];
            const int j = sel_i[sl];
            const float* wr = W_enc + (size_t)j * DIN;
            float acc = 0.f;
            #pragma unroll 8
            for (int k = 0; k < DIN; ++k)
                acc = fmaf(xc[k], wr[k], acc);
            bnd_sv[tid] = acc + b_enc[j];
        }
        __syncthreads();
        if (tid == 0) {
            int slots = 0;
            for (int m = 0; m < nb; ++m) {
                if (s_rank[bnd_sl[m]] < TOPK) ++slots;
                s_member[bnd_sl[m]] = 0;
            }
            bool used[BANDCAP];
            for (int m = 0; m < nb; ++m) used[m] = false;
            for (int s = 0; s < slots; ++s) {
                int best = -1;
                for (int m = 0; m < nb; ++m) {
                    if (used[m]) continue;
                    if (best < 0 || bnd_sv[m] > bnd_sv[best] ||
                        (bnd_sv[m] == bnd_sv[best] && sel_i[bnd_sl[m]] < sel_i[bnd_sl[best]])) best = m;
                }
                used[best] = true;
                s_member[bnd_sl[best]] = 1;
            }
        }
        __syncthreads();
    }

    // deterministic compaction (prefix count)
    if (tid < nsel && s_member[tid]) {
        int pos = 0;
        for (int m = 0; m < tid; ++m) pos += s_member[m];
        const float fv = (float)s_ex[tid];
        out_i[pos] = sel_i[tid];
        out_v[pos] = fv > 0.f ? fv : 0.f;
    }
    __syncthreads();

    // scatter
    float* orow = h_sparse + (size_t)row * HID;
    const float4 z4 = make_float4(0.f, 0.f, 0.f, 0.f);
    for (int i = tid; i < HID / 4; i += 128) ((float4*)orow)[i] = z4;
    __syncthreads();
    if (tid < TOPK) {
        orow[out_i[tid]] = out_v[tid];
        g_tidx[(size_t)row * TOPK + tid] = out_i[tid];
        g_tval[(size_t)row * TOPK + tid] = out_v[tid];
    }
}

// ======================= sparse decoder =======================
__global__ void __launch_bounds__(192) dec_kernel(
    const float* __restrict__ b_pre, float* __restrict__ xrec)
{
    const int row = blockIdx.x;
    __shared__ int   si[TOPK];
    __shared__ float svl[TOPK];
    const int tid = threadIdx.x;
    if (tid < TOPK) {
        si[tid]  = g_tidx[(size_t)row * TOPK + tid];
        svl[tid] = g_tval[(size_t)row * TOPK + tid];
    }
    __syncthreads();

    float4 acc = ((const float4*)b_pre)[tid];
    #pragma unroll 4
    for (int k = 0; k < TOPK; ++k) {
        const float v = svl[k];
        const float4 wv = ((const float4*)(g_wdecT + (size_t)si[k] * DIN))[tid];
        acc.x = fmaf(v, wv.x, acc.x);
        acc.y = fmaf(v, wv.y, acc.y);
        acc.z = fmaf(v, wv.z, acc.z);
        acc.w = fmaf(v, wv.w, acc.w);
    }
    ((float4*)(xrec + (size_t)row * DIN))[tid] = acc;
}

// ======================= launch =======================
extern "C" void kernel_launch(void* const* d_in, const int* in_sizes, int n_in,
                              void* d_out, int out_size)
{
    const float* x     = (const float*)d_in[0];
    const float* W_enc = (const float*)d_in[1];
    const float* b_enc = (const float*)d_in[2];
    const float* W_dec = (const float*)d_in[3];
    const float* b_pre = (const float*)d_in[4];

    float* out      = (float*)d_out;
    float* xrec     = out;                        // [B, 768]
    float* h_sparse = out + (size_t)BATCH * DIN;  // [B, 3840]

    cudaFuncSetAttribute(enc_gemm_wmma, cudaFuncAttributeMaxDynamicSharedMemorySize, GSMEM_BYTES);

    conv_x_kernel<<<BATCH, 192>>>(x, b_pre);
    conv_w_kernel<<<HID, 192>>>(W_enc);
    transpose_kernel<<<dim3(HID / 32, DIN / 32), dim3(32, 8)>>>(W_dec);

    enc_gemm_wmma<<<dim3(HID / GBN, BATCH / GBM), 256, GSMEM_BYTES>>>(b_enc);

    topk_kernel<<<BATCH, 128>>>(h_sparse, x, W_enc, b_pre, b_enc);
    dec_kernel<<<BATCH, 192>>>(b_pre, xrec);
}

// round 14
// speedup vs baseline: 2.5698x; 1.2768x over previous
#include <cuda_runtime.h>
#include <cuda_bf16.h>
#include <mma.h>
#include <cstdint>
#include <cstring>

using namespace nvcuda;

#define BATCH 32768
#define DIN   768
#define HID   3840
#define TOPK  64
#define NSEL  80
#define CAP   512
#define T0FILT 1.55f
#define GAPEPS 1e-4f
#define BANDCAP 32

// ---------------- scratch ----------------
__device__ float g_h[(size_t)BATCH * HID];
__device__ float g_wdecT[(size_t)HID * DIN];
__device__ int   g_tidx[(size_t)BATCH * TOPK];
__device__ float g_tval[(size_t)BATCH * TOPK];
__device__ __align__(16) __nv_bfloat16 g_xb[(size_t)BATCH * DIN];
__device__ __align__(16) __nv_bfloat16 g_wb[(size_t)HID * DIN];

// ======================= bf16 conversion kernels =======================
__global__ void __launch_bounds__(192) conv_x_kernel(const float* __restrict__ x,
                                                     const float* __restrict__ b_pre) {
    const int row = blockIdx.x;
    const int c4 = threadIdx.x;
    const float4 xv = ((const float4*)(x + (size_t)row * DIN))[c4];
    const float4 bp = ((const float4*)b_pre)[c4];
    __nv_bfloat16 h0 = __float2bfloat16(xv.x - bp.x);
    __nv_bfloat16 h1 = __float2bfloat16(xv.y - bp.y);
    __nv_bfloat16 h2 = __float2bfloat16(xv.z - bp.z);
    __nv_bfloat16 h3 = __float2bfloat16(xv.w - bp.w);
    uint2 p;
    p.x = (uint32_t)*(unsigned short*)&h0 | ((uint32_t)*(unsigned short*)&h1 << 16);
    p.y = (uint32_t)*(unsigned short*)&h2 | ((uint32_t)*(unsigned short*)&h3 << 16);
    ((uint2*)(g_xb + (size_t)row * DIN))[c4] = p;
}

__global__ void __launch_bounds__(192) conv_w_kernel(const float* __restrict__ W) {
    const int row = blockIdx.x;
    const int c4 = threadIdx.x;
    const float4 wv = ((const float4*)(W + (size_t)row * DIN))[c4];
    __nv_bfloat16 h0 = __float2bfloat16(wv.x);
    __nv_bfloat16 h1 = __float2bfloat16(wv.y);
    __nv_bfloat16 h2 = __float2bfloat16(wv.z);
    __nv_bfloat16 h3 = __float2bfloat16(wv.w);
    uint2 p;
    p.x = (uint32_t)*(unsigned short*)&h0 | ((uint32_t)*(unsigned short*)&h1 << 16);
    p.y = (uint32_t)*(unsigned short*)&h2 | ((uint32_t)*(unsigned short*)&h3 << 16);
    ((uint2*)(g_wb + (size_t)row * DIN))[c4] = p;
}

// ======================= WMMA bf16 screening GEMM (verified R11-R13) =======================
#define GBM 128
#define GBN 128
#define GBK 32
#define LDSB 40
#define BUF_ELEMS (GBM * LDSB)
#define GSMEM_BYTES (4 * BUF_ELEMS * 2)

__global__ void __launch_bounds__(256, 2) enc_gemm_wmma(const float* __restrict__ b_enc) {
    extern __shared__ char gsm[];
    __nv_bfloat16* Abuf = (__nv_bfloat16*)gsm;
    __nv_bfloat16* Bbuf = (__nv_bfloat16*)(gsm + 2 * BUF_ELEMS * 2);
    float* stage = (float*)gsm;

    const int bm = blockIdx.y * GBM;
    const int bn = blockIdx.x * GBN;
    const int tid = threadIdx.x, lane = tid & 31, wid = tid >> 5;
    const int wm = wid & 3;
    const int wn = wid >> 2;

    wmma::fragment<wmma::accumulator, 16, 16, 16, float> c[2][4];
    #pragma unroll
    for (int i = 0; i < 2; ++i)
        #pragma unroll
        for (int j = 0; j < 4; ++j) wmma::fill_fragment(c[i][j], 0.f);

    uint4 ra[2], rb[2];
    #pragma unroll
    for (int i = 0; i < 2; ++i) {
        const int idx = tid + 256 * i;
        const int r = idx >> 2, seg = idx & 3;
        ra[i] = *(const uint4*)(g_xb + (size_t)(bm + r) * DIN + seg * 8);
        rb[i] = *(const uint4*)(g_wb + (size_t)(bn + r) * DIN + seg * 8);
    }
    #pragma unroll
    for (int i = 0; i < 2; ++i) {
        const int idx = tid + 256 * i;
        const int r = idx >> 2, seg = idx & 3;
        *(uint4*)(Abuf + r * LDSB + seg * 8) = ra[i];
        *(uint4*)(Bbuf + r * LDSB + seg * 8) = rb[i];
    }
    __syncthreads();

    int buf = 0;
    const int NS = DIN / GBK;

    #pragma unroll 1
    for (int s = 0; s < NS; ++s) {
        const bool has_next = (s + 1 < NS);
        if (has_next) {
            const int k0 = (s + 1) * GBK;
            #pragma unroll
            for (int i = 0; i < 2; ++i) {
                const int idx = tid + 256 * i;
                const int r = idx >> 2, seg = idx & 3;
                ra[i] = *(const uint4*)(g_xb + (size_t)(bm + r) * DIN + k0 + seg * 8);
                rb[i] = *(const uint4*)(g_wb + (size_t)(bn + r) * DIN + k0 + seg * 8);
            }
        }

        const __nv_bfloat16* Ab = Abuf + buf * BUF_ELEMS;
        const __nv_bfloat16* Bb = Bbuf + buf * BUF_ELEMS;
        #pragma unroll
        for (int ks = 0; ks < 2; ++ks) {
            wmma::fragment<wmma::matrix_a, 16, 16, 16, __nv_bfloat16, wmma::row_major> af[2];
            wmma::fragment<wmma::matrix_b, 16, 16, 16, __nv_bfloat16, wmma::col_major> bfr[4];
            #pragma unroll
            for (int i = 0; i < 2; ++i)
                wmma::load_matrix_sync(af[i], Ab + (wm * 32 + 16 * i) * LDSB + ks * 16, LDSB);
            #pragma unroll
            for (int j = 0; j < 4; ++j)
                wmma::load_matrix_sync(bfr[j], Bb + (wn * 64 + 16 * j) * LDSB + ks * 16, LDSB);
            #pragma unroll
            for (int i = 0; i < 2; ++i)
                #pragma unroll
                for (int j = 0; j < 4; ++j)
                    wmma::mma_sync(c[i][j], af[i], bfr[j], c[i][j]);
        }

        if (has_next) {
            const int nb = buf ^ 1;
            #pragma unroll
            for (int i = 0; i < 2; ++i) {
                const int idx = tid + 256 * i;
                const int r = idx >> 2, seg = idx & 3;
                *(uint4*)(Abuf + nb * BUF_ELEMS + r * LDSB + seg * 8) = ra[i];
                *(uint4*)(Bbuf + nb * BUF_ELEMS + r * LDSB + seg * 8) = rb[i];
            }
        }
        __syncthreads();
        buf ^= 1;
    }

    float* wstage = stage + wid * 320;
    const int rr = lane >> 1;
    const int cc = (lane & 1) * 8;
    #pragma unroll
    for (int i = 0; i < 2; ++i) {
        #pragma unroll
        for (int j = 0; j < 4; ++j) {
            wmma::store_matrix_sync(wstage, c[i][j], 20, wmma::mem_row_major);
            __syncwarp();
            const int m = bm + wm * 32 + 16 * i + rr;
            const int n = bn + wn * 64 + 16 * j + cc;
            float4 v0 = *(float4*)(wstage + rr * 20 + cc);
            float4 v1 = *(float4*)(wstage + rr * 20 + cc + 4);
            const float4 be0 = *(const float4*)(b_enc + n);
            const float4 be1 = *(const float4*)(b_enc + n + 4);
            v0.x += be0.x; v0.y += be0.y; v0.z += be0.z; v0.w += be0.w;
            v1.x += be1.x; v1.y += be1.y; v1.z += be1.z; v1.w += be1.w;
            *(float4*)(g_h + (size_t)m * HID + n)     = v0;
            *(float4*)(g_h + (size_t)m * HID + n + 4) = v1;
            __syncwarp();
        }
    }
}

// ======================= W_dec [D,H] -> W_decT [H,D] =======================
__global__ void transpose_kernel(const float* __restrict__ in)
{
    __shared__ float t[32][33];
    const int bx = blockIdx.x * 32;
    const int by = blockIdx.y * 32;
    const int x = bx + threadIdx.x;
    #pragma unroll
    for (int j = 0; j < 32; j += 8)
        t[threadIdx.y + j][threadIdx.x] = in[(size_t)(by + threadIdx.y + j) * HID + x];
    __syncthreads();
    const int x2 = by + threadIdx.x;
    #pragma unroll
    for (int j = 0; j < 32; j += 8)
        g_wdecT[(size_t)(bx + threadIdx.y + j) * DIN + x2] = t[threadIdx.x][threadIdx.y + j];
}

// ======================= topk: screen -> plain fp32 rescore -> boundary band (serial fp32) =======================
__global__ void __launch_bounds__(128) topk_kernel(
    float* __restrict__ h_sparse,
    const float* __restrict__ x, const float* __restrict__ W_enc,
    const float* __restrict__ b_pre, const float* __restrict__ b_enc)
{
    const int row = blockIdx.x;
    __shared__ float xc[DIN];
    __shared__ float cv[CAP];
    __shared__ int   ci[CAP];
    __shared__ int   s_cnt, s_nsel, s_nband, s_doband;
    __shared__ int   sel_i[NSEL];
    __shared__ float s_val[NSEL];
    __shared__ int   s_rank[NSEL];
    __shared__ unsigned char s_member[NSEL];
    __shared__ float s_v63, s_v64;
    __shared__ int   bnd_sl[BANDCAP];
    __shared__ float bnd_sv[BANDCAP];
    __shared__ int   out_i[TOPK];
    __shared__ float out_v[TOPK];

    const int tid = threadIdx.x, lane = tid & 31, wrp = tid >> 5;
    const float* hr = g_h + (size_t)row * HID;

    if (tid == 0) { s_cnt = 0; s_nband = 0; s_doband = 0; s_v63 = 3.0e38f; s_v64 = -3.0e38f; }

    // exact centered x row into smem
    {
        const float4* x4 = (const float4*)(x + (size_t)row * DIN);
        const float4* b4 = (const float4*)b_pre;
        for (int i = tid; i < DIN / 4; i += 128) {
            float4 xv = x4[i], bp = b4[i];
            xv.x -= bp.x; xv.y -= bp.y; xv.z -= bp.z; xv.w -= bp.w;
            ((float4*)xc)[i] = xv;
        }
    }
    __syncthreads();

    // prefilter candidates from approx h (storage order irrelevant: rank is by (v,idx))
    for (int i = tid; i < HID / 4; i += 128) {
        float4 v = ((const float4*)hr)[i];
        const int base = i * 4;
        if (v.x > T0FILT) { int p = atomicAdd(&s_cnt, 1); if (p < CAP) { cv[p] = v.x; ci[p] = base + 0; } }
        if (v.y > T0FILT) { int p = atomicAdd(&s_cnt, 1); if (p < CAP) { cv[p] = v.y; ci[p] = base + 1; } }
        if (v.z > T0FILT) { int p = atomicAdd(&s_cnt, 1); if (p < CAP) { cv[p] = v.z; ci[p] = base + 2; } }
        if (v.w > T0FILT) { int p = atomicAdd(&s_cnt, 1); if (p < CAP) { cv[p] = v.w; ci[p] = base + 3; } }
    }
    __syncthreads();
    const int cnt = s_cnt;
    const bool fb = (cnt < TOPK) || (cnt > CAP);

    // candidate set selection
    if (!fb && cnt <= NSEL) {
        if (tid == 0) s_nsel = cnt;
        if (tid < cnt) sel_i[tid] = ci[tid];
    } else if (!fb) {
        // counting-rank top-NSEL: rank over (value desc, idx asc); ranks are unique
        if (tid == 0) s_nsel = NSEL;
        for (int c = tid; c < cnt; c += 128) {
            const float mv = cv[c];
            const int mi = ci[c];
            int rank = 0;
            for (int m = 0; m < cnt; ++m) {
                const float ov = cv[m];
                if (ov > mv || (ov == mv && ci[m] < mi)) ++rank;
            }
            if (rank < NSEL) sel_i[rank] = mi;
        }
    } else {
        // rare fallback: serial top-80 straight from g_h (scratch; clobbered)
        if (tid == 0) s_nsel = NSEL;
        if (tid < 32) {
            float* hrm = g_h + (size_t)row * HID;
            for (int it = 0; it < NSEL; ++it) {
                float best = -3.0e38f; int bi = 0x7FFFFFFF;
                for (int c = lane; c < HID; c += 32) {
                    float v = hrm[c];
                    if (v > best || (v == best && c < bi)) { best = v; bi = c; }
                }
                #pragma unroll
                for (int o = 16; o > 0; o >>= 1) {
                    float ov = __shfl_xor_sync(0xffffffffu, best, o);
                    int   oi = __shfl_xor_sync(0xffffffffu, bi, o);
                    if (ov > best || (ov == best && oi < bi)) { best = ov; bi = oi; }
                }
                if (lane == 0) { hrm[bi] = -3.0e38f; sel_i[it] = bi; }
                __syncwarp();
            }
        }
    }
    __syncthreads();
    const int nsel = s_nsel;

    // plain fp32 warp-parallel rescore (error ~1e-6 << GAPEPS band)
    for (int q = 0; q < NSEL / 4; ++q) {
        const int sl = wrp * (NSEL / 4) + q;
        if (sl < nsel) {
            const int j = sel_i[sl];
            const float4* wr4 = (const float4*)(W_enc + (size_t)j * DIN);
            const float4* xc4 = (const float4*)xc;
            float s = 0.f;
            for (int f = lane; f < DIN / 4; f += 32) {
                const float4 xv = xc4[f];
                const float4 wv = wr4[f];
                s = fmaf(xv.x, wv.x, s);
                s = fmaf(xv.y, wv.y, s);
                s = fmaf(xv.z, wv.z, s);
                s = fmaf(xv.w, wv.w, s);
            }
            #pragma unroll
            for (int o = 16; o > 0; o >>= 1)
                s += __shfl_xor_sync(0xffffffffu, s, o);
            if (lane == 0) s_val[sl] = s + b_enc[j];
        }
    }
    __syncthreads();

    // rank by value (desc, idx asc); default membership = rank < 64
    if (tid < nsel) {
        const float mv = s_val[tid];
        const int mi = sel_i[tid];
        int rank = 0;
        for (int m = 0; m < nsel; ++m) {
            const float ov = s_val[m];
            const int oi = sel_i[m];
            if (ov > mv || (ov == mv && oi < mi)) ++rank;
        }
        s_rank[tid] = rank;
        s_member[tid] = (rank < TOPK) ? 1 : 0;
        if (rank == TOPK - 1) s_v63 = mv;
        if (rank == TOPK)     s_v64 = mv;
    }
    __syncthreads();

    if (tid == 0 && nsel > TOPK && (s_v63 - s_v64) < GAPEPS) s_doband = 1;
    __syncthreads();

    if (s_doband) {
        if (tid < nsel) {
            const float v = s_val[tid];
            if (v >= s_v64 - GAPEPS && v <= s_v63 + GAPEPS) {
                int p = atomicAdd(&s_nband, 1);
                if (p < BANDCAP) bnd_sl[p] = tid;
            }
        }
        __syncthreads();
        const int nb = min(s_nband, BANDCAP);
        // serial fp32 k-ascending rescore of band members (jax-matching, R12/R13-verified)
        if (tid < nb) {
            const int sl = bnd_sl[tid];
            const int j = sel_i[sl];
            const float* wr = W_enc + (size_t)j * DIN;
            float acc = 0.f;
            #pragma unroll 8
            for (int k = 0; k < DIN; ++k)
                acc = fmaf(xc[k], wr[k], acc);
            bnd_sv[tid] = acc + b_enc[j];
        }
        __syncthreads();
        if (tid == 0) {
            int slots = 0;
            for (int m = 0; m < nb; ++m) {
                if (s_rank[bnd_sl[m]] < TOPK) ++slots;
                s_member[bnd_sl[m]] = 0;
            }
            bool used[BANDCAP];
            for (int m = 0; m < nb; ++m) used[m] = false;
            for (int s = 0; s < slots; ++s) {
                int best = -1;
                for (int m = 0; m < nb; ++m) {
                    if (used[m]) continue;
                    if (best < 0 || bnd_sv[m] > bnd_sv[best] ||
                        (bnd_sv[m] == bnd_sv[best] && sel_i[bnd_sl[m]] < sel_i[bnd_sl[best]])) best = m;
                }
                used[best] = true;
                s_member[bnd_sl[best]] = 1;
            }
        }
        __syncthreads();
    }

    // deterministic compaction (prefix count)
    if (tid < nsel && s_member[tid]) {
        int pos = 0;
        for (int m = 0; m < tid; ++m) pos += s_member[m];
        const float fv = s_val[tid];
        out_i[pos] = sel_i[tid];
        out_v[pos] = fv > 0.f ? fv : 0.f;
    }
    __syncthreads();

    // scatter
    float* orow = h_sparse + (size_t)row * HID;
    const float4 z4 = make_float4(0.f, 0.f, 0.f, 0.f);
    for (int i = tid; i < HID / 4; i += 128) ((float4*)orow)[i] = z4;
    __syncthreads();
    if (tid < TOPK) {
        orow[out_i[tid]] = out_v[tid];
        g_tidx[(size_t)row * TOPK + tid] = out_i[tid];
        g_tval[(size_t)row * TOPK + tid] = out_v[tid];
    }
}

// ======================= sparse decoder =======================
__global__ void __launch_bounds__(192) dec_kernel(
    const float* __restrict__ b_pre, float* __restrict__ xrec)
{
    const int row = blockIdx.x;
    __shared__ int   si[TOPK];
    __shared__ float svl[TOPK];
    const int tid = threadIdx.x;
    if (tid < TOPK) {
        si[tid]  = g_tidx[(size_t)row * TOPK + tid];
        svl[tid] = g_tval[(size_t)row * TOPK + tid];
    }
    __syncthreads();

    float4 acc = ((const float4*)b_pre)[tid];
    #pragma unroll 4
    for (int k = 0; k < TOPK; ++k) {
        const float v = svl[k];
        const float4 wv = ((const float4*)(g_wdecT + (size_t)si[k] * DIN))[tid];
        acc.x = fmaf(v, wv.x, acc.x);
        acc.y = fmaf(v, wv.y, acc.y);
        acc.z = fmaf(v, wv.z, acc.z);
        acc.w = fmaf(v, wv.w, acc.w);
    }
    ((float4*)(xrec + (size_t)row * DIN))[tid] = acc;
}

// ======================= launch =======================
extern "C" void kernel_launch(void* const* d_in, const int* in_sizes, int n_in,
                              void* d_out, int out_size)
{
    const float* x     = (const float*)d_in[0];
    const float* W_enc = (const float*)d_in[1];
    const float* b_enc = (const float*)d_in[2];
    const float* W_dec = (const float*)d_in[3];
    const float* b_pre = (const float*)d_in[4];

    float* out      = (float*)d_out;
    float* xrec     = out;                        // [B, 768]
    float* h_sparse = out + (size_t)BATCH * DIN;  // [B, 3840]

    cudaFuncSetAttribute(enc_gemm_wmma, cudaFuncAttributeMaxDynamicSharedMemorySize, GSMEM_BYTES);

    conv_x_kernel<<<BATCH, 192>>>(x, b_pre);
    conv_w_kernel<<<HID, 192>>>(W_enc);
    transpose_kernel<<<dim3(HID / 32, DIN / 32), dim3(32, 8)>>>(W_dec);

    enc_gemm_wmma<<<dim3(HID / GBN, BATCH / GBM), 256, GSMEM_BYTES>>>(b_enc);

    topk_kernel<<<BATCH, 128>>>(h_sparse, x, W_enc, b_pre, b_enc);
    dec_kernel<<<BATCH, 192>>>(b_pre, xrec);
}

// round 15
// speedup vs baseline: 2.6427x; 1.0284x over previous
#include <cuda_runtime.h>
#include <cuda_bf16.h>
#include <mma.h>
#include <cstdint>
#include <cstring>

using namespace nvcuda;

#define BATCH 32768
#define DIN   768
#define HID   3840
#define TOPK  64
#define NSEL  80
#define CAP   512
#define T0FILT 1.55f
#define GAPEPS 1e-4f
#define BANDCAP 32
#define TKT 256   // topk threads

// ---------------- scratch ----------------
__device__ float g_h[(size_t)BATCH * HID];
__device__ float g_wdecT[(size_t)HID * DIN];
__device__ int   g_tidx[(size_t)BATCH * TOPK];
__device__ float g_tval[(size_t)BATCH * TOPK];
__device__ __align__(16) __nv_bfloat16 g_xb[(size_t)BATCH * DIN];
__device__ __align__(16) __nv_bfloat16 g_wb[(size_t)HID * DIN];

// ======================= bf16 conversion kernels =======================
__global__ void __launch_bounds__(192) conv_x_kernel(const float* __restrict__ x,
                                                     const float* __restrict__ b_pre) {
    const int row = blockIdx.x;
    const int c4 = threadIdx.x;
    const float4 xv = ((const float4*)(x + (size_t)row * DIN))[c4];
    const float4 bp = ((const float4*)b_pre)[c4];
    __nv_bfloat16 h0 = __float2bfloat16(xv.x - bp.x);
    __nv_bfloat16 h1 = __float2bfloat16(xv.y - bp.y);
    __nv_bfloat16 h2 = __float2bfloat16(xv.z - bp.z);
    __nv_bfloat16 h3 = __float2bfloat16(xv.w - bp.w);
    uint2 p;
    p.x = (uint32_t)*(unsigned short*)&h0 | ((uint32_t)*(unsigned short*)&h1 << 16);
    p.y = (uint32_t)*(unsigned short*)&h2 | ((uint32_t)*(unsigned short*)&h3 << 16);
    ((uint2*)(g_xb + (size_t)row * DIN))[c4] = p;
}

__global__ void __launch_bounds__(192) conv_w_kernel(const float* __restrict__ W) {
    const int row = blockIdx.x;
    const int c4 = threadIdx.x;
    const float4 wv = ((const float4*)(W + (size_t)row * DIN))[c4];
    __nv_bfloat16 h0 = __float2bfloat16(wv.x);
    __nv_bfloat16 h1 = __float2bfloat16(wv.y);
    __nv_bfloat16 h2 = __float2bfloat16(wv.z);
    __nv_bfloat16 h3 = __float2bfloat16(wv.w);
    uint2 p;
    p.x = (uint32_t)*(unsigned short*)&h0 | ((uint32_t)*(unsigned short*)&h1 << 16);
    p.y = (uint32_t)*(unsigned short*)&h2 | ((uint32_t)*(unsigned short*)&h3 << 16);
    ((uint2*)(g_wb + (size_t)row * DIN))[c4] = p;
}

// ======================= WMMA bf16 screening GEMM (verified R11-R14, untouched) =======================
#define GBM 128
#define GBN 128
#define GBK 32
#define LDSB 40
#define BUF_ELEMS (GBM * LDSB)
#define GSMEM_BYTES (4 * BUF_ELEMS * 2)

__global__ void __launch_bounds__(256, 2) enc_gemm_wmma(const float* __restrict__ b_enc) {
    extern __shared__ char gsm[];
    __nv_bfloat16* Abuf = (__nv_bfloat16*)gsm;
    __nv_bfloat16* Bbuf = (__nv_bfloat16*)(gsm + 2 * BUF_ELEMS * 2);
    float* stage = (float*)gsm;

    const int bm = blockIdx.y * GBM;
    const int bn = blockIdx.x * GBN;
    const int tid = threadIdx.x, lane = tid & 31, wid = tid >> 5;
    const int wm = wid & 3;
    const int wn = wid >> 2;

    wmma::fragment<wmma::accumulator, 16, 16, 16, float> c[2][4];
    #pragma unroll
    for (int i = 0; i < 2; ++i)
        #pragma unroll
        for (int j = 0; j < 4; ++j) wmma::fill_fragment(c[i][j], 0.f);

    uint4 ra[2], rb[2];
    #pragma unroll
    for (int i = 0; i < 2; ++i) {
        const int idx = tid + 256 * i;
        const int r = idx >> 2, seg = idx & 3;
        ra[i] = *(const uint4*)(g_xb + (size_t)(bm + r) * DIN + seg * 8);
        rb[i] = *(const uint4*)(g_wb + (size_t)(bn + r) * DIN + seg * 8);
    }
    #pragma unroll
    for (int i = 0; i < 2; ++i) {
        const int idx = tid + 256 * i;
        const int r = idx >> 2, seg = idx & 3;
        *(uint4*)(Abuf + r * LDSB + seg * 8) = ra[i];
        *(uint4*)(Bbuf + r * LDSB + seg * 8) = rb[i];
    }
    __syncthreads();

    int buf = 0;
    const int NS = DIN / GBK;

    #pragma unroll 1
    for (int s = 0; s < NS; ++s) {
        const bool has_next = (s + 1 < NS);
        if (has_next) {
            const int k0 = (s + 1) * GBK;
            #pragma unroll
            for (int i = 0; i < 2; ++i) {
                const int idx = tid + 256 * i;
                const int r = idx >> 2, seg = idx & 3;
                ra[i] = *(const uint4*)(g_xb + (size_t)(bm + r) * DIN + k0 + seg * 8);
                rb[i] = *(const uint4*)(g_wb + (size_t)(bn + r) * DIN + k0 + seg * 8);
            }
        }

        const __nv_bfloat16* Ab = Abuf + buf * BUF_ELEMS;
        const __nv_bfloat16* Bb = Bbuf + buf * BUF_ELEMS;
        #pragma unroll
        for (int ks = 0; ks < 2; ++ks) {
            wmma::fragment<wmma::matrix_a, 16, 16, 16, __nv_bfloat16, wmma::row_major> af[2];
            wmma::fragment<wmma::matrix_b, 16, 16, 16, __nv_bfloat16, wmma::col_major> bfr[4];
            #pragma unroll
            for (int i = 0; i < 2; ++i)
                wmma::load_matrix_sync(af[i], Ab + (wm * 32 + 16 * i) * LDSB + ks * 16, LDSB);
            #pragma unroll
            for (int j = 0; j < 4; ++j)
                wmma::load_matrix_sync(bfr[j], Bb + (wn * 64 + 16 * j) * LDSB + ks * 16, LDSB);
            #pragma unroll
            for (int i = 0; i < 2; ++i)
                #pragma unroll
                for (int j = 0; j < 4; ++j)
                    wmma::mma_sync(c[i][j], af[i], bfr[j], c[i][j]);
        }

        if (has_next) {
            const int nb = buf ^ 1;
            #pragma unroll
            for (int i = 0; i < 2; ++i) {
                const int idx = tid + 256 * i;
                const int r = idx >> 2, seg = idx & 3;
                *(uint4*)(Abuf + nb * BUF_ELEMS + r * LDSB + seg * 8) = ra[i];
                *(uint4*)(Bbuf + nb * BUF_ELEMS + r * LDSB + seg * 8) = rb[i];
            }
        }
        __syncthreads();
        buf ^= 1;
    }

    float* wstage = stage + wid * 320;
    const int rr = lane >> 1;
    const int cc = (lane & 1) * 8;
    #pragma unroll
    for (int i = 0; i < 2; ++i) {
        #pragma unroll
        for (int j = 0; j < 4; ++j) {
            wmma::store_matrix_sync(wstage, c[i][j], 20, wmma::mem_row_major);
            __syncwarp();
            const int m = bm + wm * 32 + 16 * i + rr;
            const int n = bn + wn * 64 + 16 * j + cc;
            float4 v0 = *(float4*)(wstage + rr * 20 + cc);
            float4 v1 = *(float4*)(wstage + rr * 20 + cc + 4);
            const float4 be0 = *(const float4*)(b_enc + n);
            const float4 be1 = *(const float4*)(b_enc + n + 4);
            v0.x += be0.x; v0.y += be0.y; v0.z += be0.z; v0.w += be0.w;
            v1.x += be1.x; v1.y += be1.y; v1.z += be1.z; v1.w += be1.w;
            *(float4*)(g_h + (size_t)m * HID + n)     = v0;
            *(float4*)(g_h + (size_t)m * HID + n + 4) = v1;
            __syncwarp();
        }
    }
}

// ======================= W_dec [D,H] -> W_decT [H,D] =======================
__global__ void transpose_kernel(const float* __restrict__ in)
{
    __shared__ float t[32][33];
    const int bx = blockIdx.x * 32;
    const int by = blockIdx.y * 32;
    const int x = bx + threadIdx.x;
    #pragma unroll
    for (int j = 0; j < 32; j += 8)
        t[threadIdx.y + j][threadIdx.x] = in[(size_t)(by + threadIdx.y + j) * HID + x];
    __syncthreads();
    const int x2 = by + threadIdx.x;
    #pragma unroll
    for (int j = 0; j < 32; j += 8)
        g_wdecT[(size_t)(bx + threadIdx.y + j) * DIN + x2] = t[threadIdx.x][threadIdx.y + j];
}

// ---- one-candidate fp32 dot helper (warp-strided, unrolled: 6 independent LDG.128) ----
__device__ __forceinline__ float dot_row(const float4* __restrict__ wr4,
                                         const float4* __restrict__ xc4, int lane) {
    float4 w[6], xv[6];
    #pragma unroll
    for (int u = 0; u < 6; ++u) w[u] = wr4[lane + 32 * u];
    #pragma unroll
    for (int u = 0; u < 6; ++u) xv[u] = xc4[lane + 32 * u];
    float s = 0.f;
    #pragma unroll
    for (int u = 0; u < 6; ++u) {
        s = fmaf(xv[u].x, w[u].x, s);
        s = fmaf(xv[u].y, w[u].y, s);
        s = fmaf(xv[u].z, w[u].z, s);
        s = fmaf(xv[u].w, w[u].w, s);
    }
    return s;
}

// ======================= topk: screen -> fp32 rescore -> boundary band (serial fp32) =======================
__global__ void __launch_bounds__(TKT) topk_kernel(
    float* __restrict__ h_sparse,
    const float* __restrict__ x, const float* __restrict__ W_enc,
    const float* __restrict__ b_pre, const float* __restrict__ b_enc)
{
    const int row = blockIdx.x;
    __shared__ float xc[DIN];
    __shared__ float cv[CAP];
    __shared__ int   ci[CAP];
    __shared__ int   s_cnt, s_nsel, s_nband, s_doband;
    __shared__ int   sel_i[NSEL];
    __shared__ float s_val[NSEL];
    __shared__ int   s_rank[NSEL];
    __shared__ unsigned char s_member[NSEL];
    __shared__ float s_v63, s_v64;
    __shared__ int   bnd_sl[BANDCAP];
    __shared__ float bnd_sv[BANDCAP];
    __shared__ int   out_i[TOPK];
    __shared__ float out_v[TOPK];

    const int tid = threadIdx.x, lane = tid & 31, wrp = tid >> 5;
    const float* hr = g_h + (size_t)row * HID;

    if (tid == 0) { s_cnt = 0; s_nband = 0; s_doband = 0; s_v63 = 3.0e38f; s_v64 = -3.0e38f; }

    // exact centered x row into smem
    {
        const float4* x4 = (const float4*)(x + (size_t)row * DIN);
        const float4* b4 = (const float4*)b_pre;
        for (int i = tid; i < DIN / 4; i += TKT) {
            float4 xv = x4[i], bp = b4[i];
            xv.x -= bp.x; xv.y -= bp.y; xv.z -= bp.z; xv.w -= bp.w;
            ((float4*)xc)[i] = xv;
        }
    }
    __syncthreads();

    // prefilter candidates from approx h
    for (int i = tid; i < HID / 4; i += TKT) {
        float4 v = ((const float4*)hr)[i];
        const int base = i * 4;
        if (v.x > T0FILT) { int p = atomicAdd(&s_cnt, 1); if (p < CAP) { cv[p] = v.x; ci[p] = base + 0; } }
        if (v.y > T0FILT) { int p = atomicAdd(&s_cnt, 1); if (p < CAP) { cv[p] = v.y; ci[p] = base + 1; } }
        if (v.z > T0FILT) { int p = atomicAdd(&s_cnt, 1); if (p < CAP) { cv[p] = v.z; ci[p] = base + 2; } }
        if (v.w > T0FILT) { int p = atomicAdd(&s_cnt, 1); if (p < CAP) { cv[p] = v.w; ci[p] = base + 3; } }
    }
    __syncthreads();
    const int cnt = s_cnt;
    const bool fb = (cnt < TOPK) || (cnt > CAP);

    // candidate set selection
    if (!fb && cnt <= NSEL) {
        if (tid == 0) s_nsel = cnt;
        if (tid < cnt) sel_i[tid] = ci[tid];
    } else if (!fb) {
        if (tid == 0) s_nsel = NSEL;
        for (int c = tid; c < cnt; c += TKT) {
            const float mv = cv[c];
            const int mi = ci[c];
            int rank = 0;
            for (int m = 0; m < cnt; ++m) {
                const float ov = cv[m];
                if (ov > mv || (ov == mv && ci[m] < mi)) ++rank;
            }
            if (rank < NSEL) sel_i[rank] = mi;
        }
    } else {
        // rare fallback: serial top-80 straight from g_h (scratch; clobbered)
        if (tid == 0) s_nsel = NSEL;
        if (tid < 32) {
            float* hrm = g_h + (size_t)row * HID;
            for (int it = 0; it < NSEL; ++it) {
                float best = -3.0e38f; int bi = 0x7FFFFFFF;
                for (int c = lane; c < HID; c += 32) {
                    float v = hrm[c];
                    if (v > best || (v == best && c < bi)) { best = v; bi = c; }
                }
                #pragma unroll
                for (int o = 16; o > 0; o >>= 1) {
                    float ov = __shfl_xor_sync(0xffffffffu, best, o);
                    int   oi = __shfl_xor_sync(0xffffffffu, bi, o);
                    if (ov > best || (ov == best && oi < bi)) { best = ov; bi = oi; }
                }
                if (lane == 0) { hrm[bi] = -3.0e38f; sel_i[it] = bi; }
                __syncwarp();
            }
        }
    }
    __syncthreads();
    const int nsel = s_nsel;

    // fp32 warp-parallel rescore, 2 candidates per pass (MLP 12)
    {
        const float4* xc4 = (const float4*)xc;
        #pragma unroll 1
        for (int q0 = 0; q0 < NSEL / 8; q0 += 2) {
            const int sl0 = wrp * (NSEL / 8) + q0;
            const int sl1 = sl0 + 1;
            const bool a0 = (sl0 < nsel), a1 = (sl1 < nsel);
            const int j0 = a0 ? sel_i[sl0] : 0;
            const int j1 = a1 ? sel_i[sl1] : 0;
            float s0 = a0 ? dot_row((const float4*)(W_enc + (size_t)j0 * DIN), xc4, lane) : 0.f;
            float s1 = a1 ? dot_row((const float4*)(W_enc + (size_t)j1 * DIN), xc4, lane) : 0.f;
            #pragma unroll
            for (int o = 16; o > 0; o >>= 1) {
                s0 += __shfl_xor_sync(0xffffffffu, s0, o);
                s1 += __shfl_xor_sync(0xffffffffu, s1, o);
            }
            if (lane == 0) {
                if (a0) s_val[sl0] = s0 + b_enc[j0];
                if (a1) s_val[sl1] = s1 + b_enc[j1];
            }
        }
    }
    __syncthreads();

    // rank by value (desc, idx asc); default membership = rank < 64
    if (tid < nsel) {
        const float mv = s_val[tid];
        const int mi = sel_i[tid];
        int rank = 0;
        for (int m = 0; m < nsel; ++m) {
            const float ov = s_val[m];
            const int oi = sel_i[m];
            if (ov > mv || (ov == mv && oi < mi)) ++rank;
        }
        s_rank[tid] = rank;
        s_member[tid] = (rank < TOPK) ? 1 : 0;
        if (rank == TOPK - 1) s_v63 = mv;
        if (rank == TOPK)     s_v64 = mv;
    }
    __syncthreads();

    if (tid == 0 && nsel > TOPK && (s_v63 - s_v64) < GAPEPS) s_doband = 1;
    __syncthreads();

    if (s_doband) {
        if (tid < nsel) {
            const float v = s_val[tid];
            if (v >= s_v64 - GAPEPS && v <= s_v63 + GAPEPS) {
                int p = atomicAdd(&s_nband, 1);
                if (p < BANDCAP) bnd_sl[p] = tid;
            }
        }
        __syncthreads();
        const int nb = min(s_nband, BANDCAP);
        // serial fp32 k-ascending rescore of band members (jax-matching, R12-R14 verified)
        if (tid < nb) {
            const int sl = bnd_sl[tid];
            const int j = sel_i[sl];
            const float* wr = W_enc + (size_t)j * DIN;
            float acc = 0.f;
            #pragma unroll 8
            for (int k = 0; k < DIN; ++k)
                acc = fmaf(xc[k], wr[k], acc);
            bnd_sv[tid] = acc + b_enc[j];
        }
        __syncthreads();
        if (tid == 0) {
            int slots = 0;
            for (int m = 0; m < nb; ++m) {
                if (s_rank[bnd_sl[m]] < TOPK) ++slots;
                s_member[bnd_sl[m]] = 0;
            }
            bool used[BANDCAP];
            for (int m = 0; m < nb; ++m) used[m] = false;
            for (int s = 0; s < slots; ++s) {
                int best = -1;
                for (int m = 0; m < nb; ++m) {
                    if (used[m]) continue;
                    if (best < 0 || bnd_sv[m] > bnd_sv[best] ||
                        (bnd_sv[m] == bnd_sv[best] && sel_i[bnd_sl[m]] < sel_i[bnd_sl[best]])) best = m;
                }
                used[best] = true;
                s_member[bnd_sl[best]] = 1;
            }
        }
        __syncthreads();
    }

    // deterministic compaction (prefix count)
    if (tid < nsel && s_member[tid]) {
        int pos = 0;
        for (int m = 0; m < tid; ++m) pos += s_member[m];
        const float fv = s_val[tid];
        out_i[pos] = sel_i[tid];
        out_v[pos] = fv > 0.f ? fv : 0.f;
    }
    __syncthreads();

    // scatter
    float* orow = h_sparse + (size_t)row * HID;
    const float4 z4 = make_float4(0.f, 0.f, 0.f, 0.f);
    for (int i = tid; i < HID / 4; i += TKT) ((float4*)orow)[i] = z4;
    __syncthreads();
    if (tid < TOPK) {
        orow[out_i[tid]] = out_v[tid];
        g_tidx[(size_t)row * TOPK + tid] = out_i[tid];
        g_tval[(size_t)row * TOPK + tid] = out_v[tid];
    }
}

// ======================= sparse decoder =======================
__global__ void __launch_bounds__(192) dec_kernel(
    const float* __restrict__ b_pre, float* __restrict__ xrec)
{
    const int row = blockIdx.x;
    __shared__ int   si[TOPK];
    __shared__ float svl[TOPK];
    const int tid = threadIdx.x;
    if (tid < TOPK) {
        si[tid]  = g_tidx[(size_t)row * TOPK + tid];
        svl[tid] = g_tval[(size_t)row * TOPK + tid];
    }
    __syncthreads();

    float4 acc = ((const float4*)b_pre)[tid];
    #pragma unroll 4
    for (int k = 0; k < TOPK; ++k) {
        const float v = svl[k];
        const float4 wv = ((const float4*)(g_wdecT + (size_t)si[k] * DIN))[tid];
        acc.x = fmaf(v, wv.x, acc.x);
        acc.y = fmaf(v, wv.y, acc.y);
        acc.z = fmaf(v, wv.z, acc.z);
        acc.w = fmaf(v, wv.w, acc.w);
    }
    ((float4*)(xrec + (size_t)row * DIN))[tid] = acc;
}

// ======================= launch =======================
extern "C" void kernel_launch(void* const* d_in, const int* in_sizes, int n_in,
                              void* d_out, int out_size)
{
    const float* x     = (const float*)d_in[0];
    const float* W_enc = (const float*)d_in[1];
    const float* b_enc = (const float*)d_in[2];
    const float* W_dec = (const float*)d_in[3];
    const float* b_pre = (const float*)d_in[4];

    float* out      = (float*)d_out;
    float* xrec     = out;                        // [B, 768]
    float* h_sparse = out + (size_t)BATCH * DIN;  // [B, 3840]

    cudaFuncSetAttribute(enc_gemm_wmma, cudaFuncAttributeMaxDynamicSharedMemorySize, GSMEM_BYTES);

    conv_x_kernel<<<BATCH, 192>>>(x, b_pre);
    conv_w_kernel<<<HID, 192>>>(W_enc);
    transpose_kernel<<<dim3(HID / 32, DIN / 32), dim3(32, 8)>>>(W_dec);

    enc_gemm_wmma<<<dim3(HID / GBN, BATCH / GBM), 256, GSMEM_BYTES>>>(b_enc);

    topk_kernel<<<BATCH, TKT>>>(h_sparse, x, W_enc, b_pre, b_enc);
    dec_kernel<<<BATCH, 192>>>(b_pre, xrec);
}